// round 15
// baseline (speedup 1.0000x reference)
#include <cuda_runtime.h>
#include <math.h>
#include <stdint.h>

// ---- problem constants (fixed shapes) ----
#define T_TOK  4096     // B * Q_LEN tokens
#define HIDDEN 4096
#define NH     32
#define HD     128
#define B_SEQ  8
#define Q_LEN  512
#define BS_PG  64       // paged-cache block size
#define NBLK   16

#define MAT_ELEMS ((size_t)4096 * 4096)

// ---- scratch (device globals; allocation-free) ----
__device__ float g_q[MAT_ELEMS];
__device__ float g_k[MAT_ELEMS];
__device__ float g_v[MAT_ELEMS];
__device__ float g_attn[MAT_ELEMS];   // written tf32-rounded by attn kernel
// tf32-pre-rounded GEMM operands
__device__ float g_hid_t[MAT_ELEMS];
__device__ float g_wq_t[MAT_ELEMS];
__device__ float g_wk_t[MAT_ELEMS];
__device__ float g_wv_t[MAT_ELEMS];
__device__ float g_wo_t[MAT_ELEMS];

// ---- helpers ----
__device__ __forceinline__ uint32_t smem_u32(const void* p) {
  return (uint32_t)__cvta_generic_to_shared(p);
}
__device__ __forceinline__ void cp_async16(uint32_t dst, const void* src) {
  asm volatile("cp.async.cg.shared.global [%0], [%1], 16;\n" ::"r"(dst), "l"(src));
}
__device__ __forceinline__ float f2tf_f(float x) {
  uint32_t u;
  asm("cvt.rna.tf32.f32 %0, %1;\n" : "=r"(u) : "f"(x));
  return __uint_as_float(u);
}
// Ootomo split: hi = mantissa-truncated x (exactly tf32-representable, LOP3),
// lo = x - hi (exact residual; HW truncates it to tf32 inside the MMA).
__device__ __forceinline__ void split_tf32(float x, uint32_t& hi, uint32_t& lo) {
  uint32_t h = __float_as_uint(x) & 0xFFFFE000u;
  hi = h;
  lo = __float_as_uint(x - __uint_as_float(h));
}
__device__ __forceinline__ void mma_tf32(float& d0, float& d1, float& d2, float& d3,
                                         uint32_t a0, uint32_t a1, uint32_t a2, uint32_t a3,
                                         uint32_t b0, uint32_t b1) {
  asm volatile(
      "mma.sync.aligned.m16n8k8.row.col.f32.tf32.tf32.f32 "
      "{%0,%1,%2,%3},{%4,%5,%6,%7},{%8,%9},{%0,%1,%2,%3};\n"
      : "+f"(d0), "+f"(d1), "+f"(d2), "+f"(d3)
      : "r"(a0), "r"(a1), "r"(a2), "r"(a3), "r"(b0), "r"(b1));
}

// ============================================================================
// Batched convert fp32 -> tf32 (rna) for the 4 pre-GEMM operands.
// ============================================================================
__global__ __launch_bounds__(256) void cvt4_kernel(
    const float4* __restrict__ hid, const float4* __restrict__ wq,
    const float4* __restrict__ wk, const float4* __restrict__ wv) {
  size_t i = (size_t)blockIdx.x * 256 + threadIdx.x;
  if (i >= MAT_ELEMS / 4) return;
  const float4* src;
  float4* dst;
  switch (blockIdx.y) {
    case 0: src = hid; dst = (float4*)g_hid_t; break;
    case 1: src = wq;  dst = (float4*)g_wq_t;  break;
    case 2: src = wk;  dst = (float4*)g_wk_t;  break;
    default: src = wv; dst = (float4*)g_wv_t;  break;
  }
  float4 v = src[i];
  v.x = f2tf_f(v.x); v.y = f2tf_f(v.y); v.z = f2tf_f(v.z); v.w = f2tf_f(v.w);
  dst[i] = v;
}

__global__ __launch_bounds__(256) void cvt_tf32_kernel(const float4* __restrict__ in,
                                                       float4* __restrict__ out) {
  size_t i = (size_t)blockIdx.x * 256 + threadIdx.x;
  if (i >= MAT_ELEMS / 4) return;
  float4 v = in[i];
  v.x = f2tf_f(v.x); v.y = f2tf_f(v.y); v.z = f2tf_f(v.z); v.w = f2tf_f(v.w);
  out[i] = v;
}

// ============================================================================
// TF32 tensor-core GEMM: C = A @ B, operands PRE-ROUNDED to tf32.
// CTA tile 256x128, BK=16, 4-stage cp.async, 512 threads (16 warps = 4/SMSP),
// warp grid 4m x 4n, warp tile 64x32 (same inner loop as before).
// ============================================================================
#define GBM 256
#define GBN 128
#define GBK 16
#define GSTAGES 4
#define GLDA 20
#define GLDB 136
#define AS_STAGE (GBM * GLDA)                          // 5120 floats
#define BS_STAGE (GBK * GLDB)                          // 2176 floats
#define STAGE_FLOATS (AS_STAGE + BS_STAGE)             // 7296
#define GEMM_SMEM_BYTES (STAGE_FLOATS * GSTAGES * 4)   // 116736 B

__device__ __forceinline__ void gemm_load_stage(
    float* smem, int s, int kt, int m0, int n0, int tid,
    const float* __restrict__ A, const float* __restrict__ B) {
  const int K = 4096, N = 4096;
  float* As = smem + s * STAGE_FLOATS;
  float* Bs = As + AS_STAGE;
  int k0 = kt * GBK;
  // A: 256 rows x 16 floats = 1024 16B-chunks; 2 per thread
#pragma unroll
  for (int i = 0; i < 2; i++) {
    int c = tid + i * 512;
    int r = c >> 2, kc = (c & 3) * 4;
    cp_async16(smem_u32(As + r * GLDA + kc),
               A + (size_t)(m0 + r) * K + k0 + kc);
  }
  // B: 16 rows x 128 floats = 512 16B-chunks; 1 per thread
  {
    int c = tid;
    int kr = c >> 5, nc = (c & 31) * 4;
    cp_async16(smem_u32(Bs + kr * GLDB + nc),
               B + (size_t)(k0 + kr) * N + n0 + nc);
  }
}

__global__ __launch_bounds__(512, 1) void gemm_tf32(
    const float* __restrict__ A, const float* __restrict__ B,
    float* __restrict__ C) {
  extern __shared__ float smem[];
  const int K = 4096, N = 4096;
  int tid = threadIdx.x;
  int m0 = blockIdx.y * GBM, n0 = blockIdx.x * GBN;
  int lane = tid & 31, warp = tid >> 5;
  int g = lane >> 2, t = lane & 3;
  int wm = (warp >> 2) * 64;   // 4 warp-rows over 256 M
  int wn = (warp & 3) * 32;    // 4 warp-cols over 128 N

  float acc[4][4][4];
#pragma unroll
  for (int mi = 0; mi < 4; mi++)
#pragma unroll
    for (int ni = 0; ni < 4; ni++)
#pragma unroll
      for (int e = 0; e < 4; e++) acc[mi][ni][e] = 0.f;

  const int NT = K / GBK;
#pragma unroll
  for (int s = 0; s < GSTAGES - 1; s++) {
    gemm_load_stage(smem, s, s, m0, n0, tid, A, B);
    asm volatile("cp.async.commit_group;\n");
  }

  for (int kt = 0; kt < NT; kt++) {
    asm volatile("cp.async.wait_group %0;\n" ::"n"(GSTAGES - 2));
    __syncthreads();
    int pf = kt + GSTAGES - 1;
    if (pf < NT) gemm_load_stage(smem, pf % GSTAGES, pf, m0, n0, tid, A, B);
    asm volatile("cp.async.commit_group;\n");

    const float* As = smem + (kt % GSTAGES) * STAGE_FLOATS;
    const float* Bs = As + AS_STAGE;
#pragma unroll
    for (int kk = 0; kk < GBK; kk += 8) {
      uint32_t a[4][4], b[4][2];
#pragma unroll
      for (int mi = 0; mi < 4; mi++) {
        int r = wm + mi * 16 + g;
        a[mi][0] = __float_as_uint(As[r * GLDA + kk + t]);
        a[mi][1] = __float_as_uint(As[(r + 8) * GLDA + kk + t]);
        a[mi][2] = __float_as_uint(As[r * GLDA + kk + t + 4]);
        a[mi][3] = __float_as_uint(As[(r + 8) * GLDA + kk + t + 4]);
      }
#pragma unroll
      for (int ni = 0; ni < 4; ni++) {
        int c = wn + ni * 8 + g;
        b[ni][0] = __float_as_uint(Bs[(kk + t) * GLDB + c]);
        b[ni][1] = __float_as_uint(Bs[(kk + t + 4) * GLDB + c]);
      }
#pragma unroll
      for (int mi = 0; mi < 4; mi++)
#pragma unroll
        for (int ni = 0; ni < 4; ni++)
          mma_tf32(acc[mi][ni][0], acc[mi][ni][1], acc[mi][ni][2], acc[mi][ni][3],
                   a[mi][0], a[mi][1], a[mi][2], a[mi][3],
                   b[ni][0], b[ni][1]);
    }
  }

#pragma unroll
  for (int mi = 0; mi < 4; mi++) {
#pragma unroll
    for (int ni = 0; ni < 4; ni++) {
      int r = m0 + wm + mi * 16 + g;
      int c = n0 + wn + ni * 8 + 2 * t;
      *(float2*)(C + (size_t)r * N + c) =
          make_float2(acc[mi][ni][0], acc[mi][ni][1]);
      *(float2*)(C + (size_t)(r + 8) * N + c) =
          make_float2(acc[mi][ni][2], acc[mi][ni][3]);
    }
  }
}

// ============================================================================
// RoPE (in-place on g_q, g_k).
// ============================================================================
__global__ void rope_kernel(float* __restrict__ q, float* __restrict__ k,
                            const int* __restrict__ pos_ids) {
  int idx = blockIdx.x * 256 + threadIdx.x;
  if (idx >= T_TOK * NH * 64) return;
  int j = idx & 63;
  int th = idx >> 6;
  int t = th >> 5;
  float pos = (float)pos_ids[t];
  float inv = expf(-logf(10000.f) * (float)(2 * j) * (1.f / 128.f));
  float ang = pos * inv;
  float s, c;
  sincosf(ang, &s, &c);
  size_t base = (size_t)th * 128;
  float q1 = q[base + j], q2 = q[base + j + 64];
  q[base + j]      = q1 * c - q2 * s;
  q[base + j + 64] = q2 * c + q1 * s;
  float k1 = k[base + j], k2 = k[base + j + 64];
  k[base + j]      = k1 * c - k2 * s;
  k[base + j + 64] = k2 * c + k1 * s;
}

// ============================================================================
// Flash attention, split-tf32 mma, CROSS-TILE PIPELINED, KV-tile 64.
// (unchanged from R14 — measured ~0.93 ms)
// ============================================================================
#define ALDQ 132
#define ALDK 132                         // K addressing stride (64 rows)
#define ALDV 136                         // V addressing stride (64 rows)
#define SLD  68                          // S stride (128 rows) — fills K buf
#define KVBUF 8704                       // floats per K or V buffer
#define ASQ 0
#define ASK0 16896
#define ASK1 (ASK0 + KVBUF)              // 25600
#define ASV0 (ASK1 + KVBUF)              // 34304
#define ASV1 (ASV0 + KVBUF)              // 43008
#define ASM_ (ASV1 + KVBUF)              // 51712  Ms
#define ASL_ (ASM_ + 128)                // Ls
#define ASA_ (ASL_ + 128)                // Al
#define ASP_ (ASA_ + 128)                // Ps (int)
#define ATTN_SMEM_FLOATS (ASP_ + 128)    // 52224 -> 208896 B

__global__ __launch_bounds__(512, 1) void attn_kernel(
    const float* __restrict__ k_cache, const float* __restrict__ v_cache,
    const int* __restrict__ block_tab, const int* __restrict__ pos_ids,
    const int* __restrict__ kv_len) {
  extern __shared__ float sm[];
  float* Qs = sm + ASQ;
  float* Ms = sm + ASM_;
  float* Ls = sm + ASL_;
  float* Al = sm + ASA_;
  int* Ps = (int*)(sm + ASP_);

  int qt = blockIdx.x, h = blockIdx.y, b = blockIdx.z;
  int tid = threadIdx.x;
  int lane = tid & 31, warp = tid >> 5;
  int g = lane >> 2, t = lane & 3;
  int wm = (warp >> 2) * 32;      // 4 warps over 128 q-rows
  int wnq = (warp & 3) * 16;      // QK: 4 warps over 64 kv-cols
  int wnp = (warp & 3) * 32;      // PV: 4 warps over 128 d-cols
  int t_base = b * Q_LEN + qt * 128;

  // ---- Q tile [128 x 128] via cp.async (group Q) ----
#pragma unroll
  for (int j = 0; j < 8; j++) {
    int i = tid + j * 512;
    int r = i >> 5, d4 = (i & 31) * 4;
    cp_async16(smem_u32(Qs + r * ALDQ + d4),
               g_q + (size_t)(t_base + r) * HIDDEN + h * HD + d4);
  }
  asm volatile("cp.async.commit_group;\n");
  if (tid < 128) {
    Ps[tid] = pos_ids[t_base + tid];
    Ms[tid] = -1e30f;
    Ls[tid] = 0.f;
  }
  __syncthreads();  // Ps visible

  int kvl = kv_len[b];
  int maxp = Ps[127];  // positions consecutive within a q-tile
  int nt = min(maxp / 64 + 1, (kvl + 63) / 64);
  if (nt > 16) nt = 16;

  // ---- prefetch KV tile 0 (group G0) ----
  {
    int blk = block_tab[b * NBLK + 0];  // tile 0 is always history
    const float* kb = k_cache + ((size_t)blk * BS_PG * NH + h) * HD;
    const float* vb = v_cache + ((size_t)blk * BS_PG * NH + h) * HD;
#pragma unroll
    for (int j = 0; j < 4; j++) {
      int i = tid + j * 512;
      int r = i >> 5, d4 = (i & 31) * 4;
      cp_async16(smem_u32(sm + ASK0 + r * ALDK + d4), kb + (size_t)r * NH * HD + d4);
      cp_async16(smem_u32(sm + ASV0 + r * ALDV + d4), vb + (size_t)r * NH * HD + d4);
    }
  }
  asm volatile("cp.async.commit_group;\n");

  float o[2][4][4];
#pragma unroll
  for (int mi = 0; mi < 2; mi++)
#pragma unroll
    for (int ni = 0; ni < 4; ni++)
#pragma unroll
      for (int e = 0; e < 4; e++) o[mi][ni][e] = 0.f;

  const float scale = 0.08838834764831845f;  // 1/sqrt(128)

  for (int kt = 0; kt < nt; kt++) {
    // ---- prefetch tile kt+1 into the other buffers ----
    if (kt + 1 < nt) {
      int nkt = kt + 1;
      int koff = (nkt & 1) ? ASK1 : ASK0;
      int voff = (nkt & 1) ? ASV1 : ASV0;
      const float *kb, *vb;
      size_t rs;
      if (nkt < 8) {
        int blk = block_tab[b * NBLK + nkt];
        kb = k_cache + ((size_t)blk * BS_PG * NH + h) * HD;
        vb = v_cache + ((size_t)blk * BS_PG * NH + h) * HD;
        rs = (size_t)NH * HD;
      } else {
        kb = g_k + (size_t)(b * Q_LEN + (nkt - 8) * 64) * HIDDEN + h * HD;
        vb = g_v + (size_t)(b * Q_LEN + (nkt - 8) * 64) * HIDDEN + h * HD;
        rs = HIDDEN;
      }
#pragma unroll
      for (int j = 0; j < 4; j++) {
        int i = tid + j * 512;
        int r = i >> 5, d4 = (i & 31) * 4;
        cp_async16(smem_u32(sm + koff + r * ALDK + d4), kb + (size_t)r * rs + d4);
        cp_async16(smem_u32(sm + voff + r * ALDV + d4), vb + (size_t)r * rs + d4);
      }
      asm volatile("cp.async.commit_group;\n");
      asm volatile("cp.async.wait_group 1;\n");   // tile kt ready; kt+1 in flight
    } else {
      asm volatile("cp.async.wait_group 0;\n");
    }
    __syncthreads();

    float* Ks = sm + ((kt & 1) ? ASK1 : ASK0);
    float* Vs = sm + ((kt & 1) ? ASV1 : ASV0);
    float* Ss = Ks;  // S overwrites K after QK

    // ---- S = Q K^T (128x64), warp tile 32x16, split-tf32 3-pass ----
    float s_[2][2][4];
#pragma unroll
    for (int mi = 0; mi < 2; mi++)
#pragma unroll
      for (int ni = 0; ni < 2; ni++)
#pragma unroll
        for (int e = 0; e < 4; e++) s_[mi][ni][e] = 0.f;

#pragma unroll
    for (int kk = 0; kk < 128; kk += 8) {
      uint32_t ah[2][4], al[2][4], bh[2][2], bl[2][2];
#pragma unroll
      for (int mi = 0; mi < 2; mi++) {
        int r = wm + mi * 16 + g;
        split_tf32(Qs[r * ALDQ + kk + t],           ah[mi][0], al[mi][0]);
        split_tf32(Qs[(r + 8) * ALDQ + kk + t],     ah[mi][1], al[mi][1]);
        split_tf32(Qs[r * ALDQ + kk + t + 4],       ah[mi][2], al[mi][2]);
        split_tf32(Qs[(r + 8) * ALDQ + kk + t + 4], ah[mi][3], al[mi][3]);
      }
#pragma unroll
      for (int ni = 0; ni < 2; ni++) {
        int c = wnq + ni * 8 + g;
        split_tf32(Ks[c * ALDK + kk + t],     bh[ni][0], bl[ni][0]);
        split_tf32(Ks[c * ALDK + kk + t + 4], bh[ni][1], bl[ni][1]);
      }
#pragma unroll
      for (int mi = 0; mi < 2; mi++)
#pragma unroll
        for (int ni = 0; ni < 2; ni++) {
          mma_tf32(s_[mi][ni][0], s_[mi][ni][1], s_[mi][ni][2], s_[mi][ni][3],
                   ah[mi][0], ah[mi][1], ah[mi][2], ah[mi][3],
                   bh[ni][0], bh[ni][1]);
          mma_tf32(s_[mi][ni][0], s_[mi][ni][1], s_[mi][ni][2], s_[mi][ni][3],
                   ah[mi][0], ah[mi][1], ah[mi][2], ah[mi][3],
                   bl[ni][0], bl[ni][1]);
          mma_tf32(s_[mi][ni][0], s_[mi][ni][1], s_[mi][ni][2], s_[mi][ni][3],
                   al[mi][0], al[mi][1], al[mi][2], al[mi][3],
                   bh[ni][0], bh[ni][1]);
        }
    }
    __syncthreads();  // K reads done; buffer reusable for S

    // ---- scale + mask + stage S (128 x 64, stride SLD) ----
#pragma unroll
    for (int mi = 0; mi < 2; mi++) {
      int r = wm + mi * 16 + g;
      int qp0 = Ps[r], qp1 = Ps[r + 8];
#pragma unroll
      for (int ni = 0; ni < 2; ni++) {
        int c = wnq + ni * 8 + 2 * t;
        int kvp0 = kt * 64 + c, kvp1 = kvp0 + 1;
        float e0 = s_[mi][ni][0] * scale;
        float e1 = s_[mi][ni][1] * scale;
        float e2 = s_[mi][ni][2] * scale;
        float e3 = s_[mi][ni][3] * scale;
        if (kvp0 > qp0 || kvp0 >= kvl) e0 = -1e30f;
        if (kvp1 > qp0 || kvp1 >= kvl) e1 = -1e30f;
        if (kvp0 > qp1 || kvp0 >= kvl) e2 = -1e30f;
        if (kvp1 > qp1 || kvp1 >= kvl) e3 = -1e30f;
        *(float2*)(&Ss[r * SLD + c]) = make_float2(e0, e1);
        *(float2*)(&Ss[(r + 8) * SLD + c]) = make_float2(e2, e3);
      }
    }
    __syncthreads();

    // ---- online softmax: 4 threads/row, 16 cols each ----
    {
      int row = tid >> 2, seg = tid & 3;
      float* Sr = &Ss[row * SLD + seg * 16];
      float mx = -1e30f;
#pragma unroll
      for (int i4 = 0; i4 < 4; i4++) {
        float4 vv = *(float4*)(&Sr[i4 * 4]);
        mx = fmaxf(mx, fmaxf(fmaxf(vv.x, vv.y), fmaxf(vv.z, vv.w)));
      }
      mx = fmaxf(mx, __shfl_xor_sync(0xffffffffu, mx, 1));
      mx = fmaxf(mx, __shfl_xor_sync(0xffffffffu, mx, 2));
      float m_old = Ms[row];
      float m_new = fmaxf(m_old, mx);
      float sum = 0.f;
#pragma unroll
      for (int i4 = 0; i4 < 4; i4++) {
        float4 vv = *(float4*)(&Sr[i4 * 4]);
        vv.x = __expf(vv.x - m_new);
        vv.y = __expf(vv.y - m_new);
        vv.z = __expf(vv.z - m_new);
        vv.w = __expf(vv.w - m_new);
        *(float4*)(&Sr[i4 * 4]) = vv;
        sum += vv.x + vv.y + vv.z + vv.w;
      }
      sum += __shfl_xor_sync(0xffffffffu, sum, 1);
      sum += __shfl_xor_sync(0xffffffffu, sum, 2);
      if (seg == 0) {
        float alpha = __expf(m_old - m_new);
        Al[row] = alpha;
        Ls[row] = Ls[row] * alpha + sum;
        Ms[row] = m_new;
      }
    }
    __syncthreads();

    // ---- rescale O, then O += P(128x64) @ V(64x128), warp tile 32x32 ----
#pragma unroll
    for (int mi = 0; mi < 2; mi++) {
      int r = wm + mi * 16 + g;
      float a0 = Al[r], a1 = Al[r + 8];
#pragma unroll
      for (int ni = 0; ni < 4; ni++) {
        o[mi][ni][0] *= a0; o[mi][ni][1] *= a0;
        o[mi][ni][2] *= a1; o[mi][ni][3] *= a1;
      }
    }
#pragma unroll
    for (int kk = 0; kk < 64; kk += 8) {
      uint32_t ah[2][4], al[2][4], bh[4][2], bl[4][2];
#pragma unroll
      for (int mi = 0; mi < 2; mi++) {
        int r = wm + mi * 16 + g;
        split_tf32(Ss[r * SLD + kk + t],           ah[mi][0], al[mi][0]);
        split_tf32(Ss[(r + 8) * SLD + kk + t],     ah[mi][1], al[mi][1]);
        split_tf32(Ss[r * SLD + kk + t + 4],       ah[mi][2], al[mi][2]);
        split_tf32(Ss[(r + 8) * SLD + kk + t + 4], ah[mi][3], al[mi][3]);
      }
#pragma unroll
      for (int ni = 0; ni < 4; ni++) {
        int c = wnp + ni * 8 + g;
        split_tf32(Vs[(kk + t) * ALDV + c],     bh[ni][0], bl[ni][0]);
        split_tf32(Vs[(kk + t + 4) * ALDV + c], bh[ni][1], bl[ni][1]);
      }
#pragma unroll
      for (int mi = 0; mi < 2; mi++)
#pragma unroll
        for (int ni = 0; ni < 4; ni++) {
          mma_tf32(o[mi][ni][0], o[mi][ni][1], o[mi][ni][2], o[mi][ni][3],
                   ah[mi][0], ah[mi][1], ah[mi][2], ah[mi][3],
                   bh[ni][0], bh[ni][1]);
          mma_tf32(o[mi][ni][0], o[mi][ni][1], o[mi][ni][2], o[mi][ni][3],
                   ah[mi][0], ah[mi][1], ah[mi][2], ah[mi][3],
                   bl[ni][0], bl[ni][1]);
          mma_tf32(o[mi][ni][0], o[mi][ni][1], o[mi][ni][2], o[mi][ni][3],
                   al[mi][0], al[mi][1], al[mi][2], al[mi][3],
                   bh[ni][0], bh[ni][1]);
        }
    }
    __syncthreads();  // S/V reads done before tile kt+1's prefetch overwrites
  }

  // ---- normalize + tf32-round + write ----
#pragma unroll
  for (int mi = 0; mi < 2; mi++) {
    int r = wm + mi * 16 + g;
    float il0 = 1.f / Ls[r], il1 = 1.f / Ls[r + 8];
#pragma unroll
    for (int ni = 0; ni < 4; ni++) {
      int c = wnp + ni * 8 + 2 * t;
      float* d0 = g_attn + (size_t)(t_base + r) * HIDDEN + h * HD + c;
      float* d1 = g_attn + (size_t)(t_base + r + 8) * HIDDEN + h * HD + c;
      *(float2*)d0 = make_float2(f2tf_f(o[mi][ni][0] * il0), f2tf_f(o[mi][ni][1] * il0));
      *(float2*)d1 = make_float2(f2tf_f(o[mi][ni][2] * il1), f2tf_f(o[mi][ni][3] * il1));
    }
  }
}

// ============================================================================
extern "C" void kernel_launch(void* const* d_in, const int* in_sizes, int n_in,
                              void* d_out, int out_size) {
  const float* hidden = (const float*)d_in[0];
  const float* Wq = (const float*)d_in[1];
  const float* Wk = (const float*)d_in[2];
  const float* Wv = (const float*)d_in[3];
  const float* Wo = (const float*)d_in[4];
  const float* kc = (const float*)d_in[5];
  const float* vc = (const float*)d_in[6];
  const int* btab = (const int*)d_in[7];
  const int* pos = (const int*)d_in[8];
  const int* kvlen = (const int*)d_in[9];
  float* out = (float*)d_out;

  float *q, *k, *v, *attn, *hid_t, *wq_t, *wk_t, *wv_t, *wo_t;
  cudaGetSymbolAddress((void**)&q, g_q);
  cudaGetSymbolAddress((void**)&k, g_k);
  cudaGetSymbolAddress((void**)&v, g_v);
  cudaGetSymbolAddress((void**)&attn, g_attn);
  cudaGetSymbolAddress((void**)&hid_t, g_hid_t);
  cudaGetSymbolAddress((void**)&wq_t, g_wq_t);
  cudaGetSymbolAddress((void**)&wk_t, g_wk_t);
  cudaGetSymbolAddress((void**)&wv_t, g_wv_t);
  cudaGetSymbolAddress((void**)&wo_t, g_wo_t);

  cudaFuncSetAttribute(gemm_tf32, cudaFuncAttributeMaxDynamicSharedMemorySize,
                       GEMM_SMEM_BYTES);
  cudaFuncSetAttribute(attn_kernel, cudaFuncAttributeMaxDynamicSharedMemorySize,
                       ATTN_SMEM_FLOATS * 4);

  // one batched cvt launch (index 0) -> gemms occupy launch indices 1-3
  int cvt_grid = (int)((MAT_ELEMS / 4 + 255) / 256);
  {
    dim3 gc(cvt_grid, 4);
    cvt4_kernel<<<gc, 256>>>((const float4*)hidden, (const float4*)Wq,
                             (const float4*)Wk, (const float4*)Wv);
  }

  dim3 gg(32, 16);  // N/128, M/256
  gemm_tf32<<<gg, 512, GEMM_SMEM_BYTES>>>(hid_t, wq_t, q);
  gemm_tf32<<<gg, 512, GEMM_SMEM_BYTES>>>(hid_t, wk_t, k);
  gemm_tf32<<<gg, 512, GEMM_SMEM_BYTES>>>(hid_t, wv_t, v);

  rope_kernel<<<(T_TOK * NH * 64 + 255) / 256, 256>>>(q, k, pos);

  dim3 ga(4, NH, B_SEQ);  // (q-tile of 128, head, seq)
  attn_kernel<<<ga, 512, ATTN_SMEM_FLOATS * 4>>>(kc, vc, btab, pos, kvlen);

  cvt_tf32_kernel<<<cvt_grid, 256>>>((const float4*)Wo, (float4*)wo_t);
  gemm_tf32<<<gg, 512, GEMM_SMEM_BYTES>>>(attn, wo_t, out);
}

// round 17
// speedup vs baseline: 1.8819x; 1.8819x over previous
#include <cuda_runtime.h>
#include <math.h>
#include <stdint.h>

// ---- problem constants (fixed shapes) ----
#define T_TOK  4096     // B * Q_LEN tokens
#define HIDDEN 4096
#define NH     32
#define HD     128
#define B_SEQ  8
#define Q_LEN  512
#define BS_PG  64       // paged-cache block size
#define NBLK   16

#define MAT_ELEMS ((size_t)4096 * 4096)

// ---- scratch (device globals; allocation-free) ----
__device__ float g_q[MAT_ELEMS];
__device__ float g_k[MAT_ELEMS];
__device__ float g_v[MAT_ELEMS];
__device__ float g_attn[MAT_ELEMS];   // written tf32-rounded by attn kernel
// tf32-pre-rounded GEMM operands
__device__ float g_hid_t[MAT_ELEMS];
__device__ float g_wq_t[MAT_ELEMS];
__device__ float g_wk_t[MAT_ELEMS];
__device__ float g_wv_t[MAT_ELEMS];
__device__ float g_wo_t[MAT_ELEMS];

// ---- helpers ----
__device__ __forceinline__ uint32_t smem_u32(const void* p) {
  return (uint32_t)__cvta_generic_to_shared(p);
}
__device__ __forceinline__ void cp_async16(uint32_t dst, const void* src) {
  asm volatile("cp.async.cg.shared.global [%0], [%1], 16;\n" ::"r"(dst), "l"(src));
}
__device__ __forceinline__ float f2tf_f(float x) {
  uint32_t u;
  asm("cvt.rna.tf32.f32 %0, %1;\n" : "=r"(u) : "f"(x));
  return __uint_as_float(u);
}
// Ootomo split: hi = mantissa-truncated x (exactly tf32-representable, LOP3),
// lo = x - hi (exact residual; HW truncates it to tf32 inside the MMA).
__device__ __forceinline__ void split_tf32(float x, uint32_t& hi, uint32_t& lo) {
  uint32_t h = __float_as_uint(x) & 0xFFFFE000u;
  hi = h;
  lo = __float_as_uint(x - __uint_as_float(h));
}
__device__ __forceinline__ void mma_tf32(float& d0, float& d1, float& d2, float& d3,
                                         uint32_t a0, uint32_t a1, uint32_t a2, uint32_t a3,
                                         uint32_t b0, uint32_t b1) {
  asm volatile(
      "mma.sync.aligned.m16n8k8.row.col.f32.tf32.tf32.f32 "
      "{%0,%1,%2,%3},{%4,%5,%6,%7},{%8,%9},{%0,%1,%2,%3};\n"
      : "+f"(d0), "+f"(d1), "+f"(d2), "+f"(d3)
      : "r"(a0), "r"(a1), "r"(a2), "r"(a3), "r"(b0), "r"(b1));
}

// ============================================================================
// Batched convert fp32 -> tf32 (rna) for the 4 pre-GEMM operands.
// ============================================================================
__global__ __launch_bounds__(256) void cvt4_kernel(
    const float4* __restrict__ hid, const float4* __restrict__ wq,
    const float4* __restrict__ wk, const float4* __restrict__ wv) {
  size_t i = (size_t)blockIdx.x * 256 + threadIdx.x;
  if (i >= MAT_ELEMS / 4) return;
  const float4* src;
  float4* dst;
  switch (blockIdx.y) {
    case 0: src = hid; dst = (float4*)g_hid_t; break;
    case 1: src = wq;  dst = (float4*)g_wq_t;  break;
    case 2: src = wk;  dst = (float4*)g_wk_t;  break;
    default: src = wv; dst = (float4*)g_wv_t;  break;
  }
  float4 v = src[i];
  v.x = f2tf_f(v.x); v.y = f2tf_f(v.y); v.z = f2tf_f(v.z); v.w = f2tf_f(v.w);
  dst[i] = v;
}

__global__ __launch_bounds__(256) void cvt_tf32_kernel(const float4* __restrict__ in,
                                                       float4* __restrict__ out) {
  size_t i = (size_t)blockIdx.x * 256 + threadIdx.x;
  if (i >= MAT_ELEMS / 4) return;
  float4 v = in[i];
  v.x = f2tf_f(v.x); v.y = f2tf_f(v.y); v.z = f2tf_f(v.z); v.w = f2tf_f(v.w);
  out[i] = v;
}

// ============================================================================
// TF32 tensor-core GEMM: C = A @ B, operands PRE-ROUNDED to tf32.
// CTA tile 128x128, BK=16, 3-stage cp.async, 256 threads, 2 CTAs/SM.
// K-lane permutation: mma lane t <-> physical col 2t, lane t+4 <-> col 2t+1
// (applied consistently to A cols and B rows; contraction order-invariant).
// -> A fragment pair (t, t+4) is ONE LDS.64. GLDA=40 makes the LDS.64
// conflict-free per 16-lane phase; GLDB=132 makes permuted B rows
// conflict-free.
// ============================================================================
#define GBM 128
#define GBN 128
#define GBK 16
#define GSTAGES 3
#define GLDA 40
#define GLDB 132
#define AS_STAGE (GBM * GLDA)                          // 5120 floats
#define BS_STAGE (GBK * GLDB)                          // 2112 floats
#define STAGE_FLOATS (AS_STAGE + BS_STAGE)             // 7232
#define GEMM_SMEM_BYTES (STAGE_FLOATS * GSTAGES * 4)   // 86784 B (x2 CTAs ok)

__device__ __forceinline__ void gemm_load_stage(
    float* smem, int s, int kt, int m0, int n0, int tid,
    const float* __restrict__ A, const float* __restrict__ B) {
  const int K = 4096, N = 4096;
  float* As = smem + s * STAGE_FLOATS;
  float* Bs = As + AS_STAGE;
  int k0 = kt * GBK;
#pragma unroll
  for (int i = 0; i < 2; i++) {
    int c = tid + i * 256;
    int r = c >> 2, kc = (c & 3) * 4;
    cp_async16(smem_u32(As + r * GLDA + kc),
               A + (size_t)(m0 + r) * K + k0 + kc);
  }
#pragma unroll
  for (int i = 0; i < 2; i++) {
    int c = tid + i * 256;
    int kr = c >> 5, nc = (c & 31) * 4;
    cp_async16(smem_u32(Bs + kr * GLDB + nc),
               B + (size_t)(k0 + kr) * N + n0 + nc);
  }
}

__global__ __launch_bounds__(256, 2) void gemm_tf32(
    const float* __restrict__ A, const float* __restrict__ B,
    float* __restrict__ C) {
  extern __shared__ float smem[];
  const int K = 4096, N = 4096;
  int tid = threadIdx.x;
  int m0 = blockIdx.y * GBM, n0 = blockIdx.x * GBN;
  int lane = tid & 31, warp = tid >> 5;
  int g = lane >> 2, t = lane & 3;
  int wm = (warp & 1) * 64;
  int wn = (warp >> 1) * 32;

  float acc[4][4][4];
#pragma unroll
  for (int mi = 0; mi < 4; mi++)
#pragma unroll
    for (int ni = 0; ni < 4; ni++)
#pragma unroll
      for (int e = 0; e < 4; e++) acc[mi][ni][e] = 0.f;

  const int NT = K / GBK;
#pragma unroll
  for (int s = 0; s < GSTAGES - 1; s++) {
    gemm_load_stage(smem, s, s, m0, n0, tid, A, B);
    asm volatile("cp.async.commit_group;\n");
  }

  for (int kt = 0; kt < NT; kt++) {
    asm volatile("cp.async.wait_group %0;\n" ::"n"(GSTAGES - 2));
    __syncthreads();
    int pf = kt + GSTAGES - 1;
    if (pf < NT) gemm_load_stage(smem, pf % GSTAGES, pf, m0, n0, tid, A, B);
    asm volatile("cp.async.commit_group;\n");

    const float* As = smem + (kt % GSTAGES) * STAGE_FLOATS;
    const float* Bs = As + AS_STAGE;
#pragma unroll
    for (int kk = 0; kk < GBK; kk += 8) {
      uint32_t a[4][4], b[4][2];
#pragma unroll
      for (int mi = 0; mi < 4; mi++) {
        int r = wm + mi * 16 + g;
        // permuted pair: lanes (t, t+4) <-> cols (kk+2t, kk+2t+1): one LDS.64
        float2 p0 = *(const float2*)(As + r * GLDA + kk + 2 * t);
        float2 p1 = *(const float2*)(As + (r + 8) * GLDA + kk + 2 * t);
        a[mi][0] = __float_as_uint(p0.x);
        a[mi][2] = __float_as_uint(p0.y);
        a[mi][1] = __float_as_uint(p1.x);
        a[mi][3] = __float_as_uint(p1.y);
      }
#pragma unroll
      for (int ni = 0; ni < 4; ni++) {
        int c = wn + ni * 8 + g;
        b[ni][0] = __float_as_uint(Bs[(kk + 2 * t) * GLDB + c]);
        b[ni][1] = __float_as_uint(Bs[(kk + 2 * t + 1) * GLDB + c]);
      }
#pragma unroll
      for (int mi = 0; mi < 4; mi++)
#pragma unroll
        for (int ni = 0; ni < 4; ni++)
          mma_tf32(acc[mi][ni][0], acc[mi][ni][1], acc[mi][ni][2], acc[mi][ni][3],
                   a[mi][0], a[mi][1], a[mi][2], a[mi][3],
                   b[ni][0], b[ni][1]);
    }
  }

#pragma unroll
  for (int mi = 0; mi < 4; mi++) {
#pragma unroll
    for (int ni = 0; ni < 4; ni++) {
      int r = m0 + wm + mi * 16 + g;
      int c = n0 + wn + ni * 8 + 2 * t;
      *(float2*)(C + (size_t)r * N + c) =
          make_float2(acc[mi][ni][0], acc[mi][ni][1]);
      *(float2*)(C + (size_t)(r + 8) * N + c) =
          make_float2(acc[mi][ni][2], acc[mi][ni][3]);
    }
  }
}

// ============================================================================
// RoPE (in-place on g_q, g_k).
// ============================================================================
__global__ void rope_kernel(float* __restrict__ q, float* __restrict__ k,
                            const int* __restrict__ pos_ids) {
  int idx = blockIdx.x * 256 + threadIdx.x;
  if (idx >= T_TOK * NH * 64) return;
  int j = idx & 63;
  int th = idx >> 6;
  int t = th >> 5;
  float pos = (float)pos_ids[t];
  float inv = expf(-logf(10000.f) * (float)(2 * j) * (1.f / 128.f));
  float ang = pos * inv;
  float s, c;
  sincosf(ang, &s, &c);
  size_t base = (size_t)th * 128;
  float q1 = q[base + j], q2 = q[base + j + 64];
  q[base + j]      = q1 * c - q2 * s;
  q[base + j + 64] = q2 * c + q1 * s;
  float k1 = k[base + j], k2 = k[base + j + 64];
  k[base + j]      = k1 * c - k2 * s;
  k[base + j + 64] = k2 * c + k1 * s;
}

// ============================================================================
// Flash attention, split-tf32 mma, CROSS-TILE PIPELINED, KV-tile 64.
// (R14 version, measured ~0.93 ms — unchanged)
// ============================================================================
#define ALDQ 132
#define ALDK 132                         // K addressing stride (64 rows)
#define ALDV 136                         // V addressing stride (64 rows)
#define SLD  68                          // S stride (128 rows) — fills K buf
#define KVBUF 8704                       // floats per K or V buffer
#define ASQ 0
#define ASK0 16896
#define ASK1 (ASK0 + KVBUF)              // 25600
#define ASV0 (ASK1 + KVBUF)              // 34304
#define ASV1 (ASV0 + KVBUF)              // 43008
#define ASM_ (ASV1 + KVBUF)              // 51712  Ms
#define ASL_ (ASM_ + 128)                // Ls
#define ASA_ (ASL_ + 128)                // Al
#define ASP_ (ASA_ + 128)                // Ps (int)
#define ATTN_SMEM_FLOATS (ASP_ + 128)    // 52224 -> 208896 B

__global__ __launch_bounds__(512, 1) void attn_kernel(
    const float* __restrict__ k_cache, const float* __restrict__ v_cache,
    const int* __restrict__ block_tab, const int* __restrict__ pos_ids,
    const int* __restrict__ kv_len) {
  extern __shared__ float sm[];
  float* Qs = sm + ASQ;
  float* Ms = sm + ASM_;
  float* Ls = sm + ASL_;
  float* Al = sm + ASA_;
  int* Ps = (int*)(sm + ASP_);

  int qt = blockIdx.x, h = blockIdx.y, b = blockIdx.z;
  int tid = threadIdx.x;
  int lane = tid & 31, warp = tid >> 5;
  int g = lane >> 2, t = lane & 3;
  int wm = (warp >> 2) * 32;      // 4 warps over 128 q-rows
  int wnq = (warp & 3) * 16;      // QK: 4 warps over 64 kv-cols
  int wnp = (warp & 3) * 32;      // PV: 4 warps over 128 d-cols
  int t_base = b * Q_LEN + qt * 128;

  // ---- Q tile [128 x 128] via cp.async (group Q) ----
#pragma unroll
  for (int j = 0; j < 8; j++) {
    int i = tid + j * 512;
    int r = i >> 5, d4 = (i & 31) * 4;
    cp_async16(smem_u32(Qs + r * ALDQ + d4),
               g_q + (size_t)(t_base + r) * HIDDEN + h * HD + d4);
  }
  asm volatile("cp.async.commit_group;\n");
  if (tid < 128) {
    Ps[tid] = pos_ids[t_base + tid];
    Ms[tid] = -1e30f;
    Ls[tid] = 0.f;
  }
  __syncthreads();  // Ps visible

  int kvl = kv_len[b];
  int maxp = Ps[127];  // positions consecutive within a q-tile
  int nt = min(maxp / 64 + 1, (kvl + 63) / 64);
  if (nt > 16) nt = 16;

  // ---- prefetch KV tile 0 (group G0) ----
  {
    int blk = block_tab[b * NBLK + 0];  // tile 0 is always history
    const float* kb = k_cache + ((size_t)blk * BS_PG * NH + h) * HD;
    const float* vb = v_cache + ((size_t)blk * BS_PG * NH + h) * HD;
#pragma unroll
    for (int j = 0; j < 4; j++) {
      int i = tid + j * 512;
      int r = i >> 5, d4 = (i & 31) * 4;
      cp_async16(smem_u32(sm + ASK0 + r * ALDK + d4), kb + (size_t)r * NH * HD + d4);
      cp_async16(smem_u32(sm + ASV0 + r * ALDV + d4), vb + (size_t)r * NH * HD + d4);
    }
  }
  asm volatile("cp.async.commit_group;\n");

  float o[2][4][4];
#pragma unroll
  for (int mi = 0; mi < 2; mi++)
#pragma unroll
    for (int ni = 0; ni < 4; ni++)
#pragma unroll
      for (int e = 0; e < 4; e++) o[mi][ni][e] = 0.f;

  const float scale = 0.08838834764831845f;  // 1/sqrt(128)

  for (int kt = 0; kt < nt; kt++) {
    // ---- prefetch tile kt+1 into the other buffers ----
    if (kt + 1 < nt) {
      int nkt = kt + 1;
      int koff = (nkt & 1) ? ASK1 : ASK0;
      int voff = (nkt & 1) ? ASV1 : ASV0;
      const float *kb, *vb;
      size_t rs;
      if (nkt < 8) {
        int blk = block_tab[b * NBLK + nkt];
        kb = k_cache + ((size_t)blk * BS_PG * NH + h) * HD;
        vb = v_cache + ((size_t)blk * BS_PG * NH + h) * HD;
        rs = (size_t)NH * HD;
      } else {
        kb = g_k + (size_t)(b * Q_LEN + (nkt - 8) * 64) * HIDDEN + h * HD;
        vb = g_v + (size_t)(b * Q_LEN + (nkt - 8) * 64) * HIDDEN + h * HD;
        rs = HIDDEN;
      }
#pragma unroll
      for (int j = 0; j < 4; j++) {
        int i = tid + j * 512;
        int r = i >> 5, d4 = (i & 31) * 4;
        cp_async16(smem_u32(sm + koff + r * ALDK + d4), kb + (size_t)r * rs + d4);
        cp_async16(smem_u32(sm + voff + r * ALDV + d4), vb + (size_t)r * rs + d4);
      }
      asm volatile("cp.async.commit_group;\n");
      asm volatile("cp.async.wait_group 1;\n");   // tile kt ready; kt+1 in flight
    } else {
      asm volatile("cp.async.wait_group 0;\n");
    }
    __syncthreads();

    float* Ks = sm + ((kt & 1) ? ASK1 : ASK0);
    float* Vs = sm + ((kt & 1) ? ASV1 : ASV0);
    float* Ss = Ks;  // S overwrites K after QK

    // ---- S = Q K^T (128x64), warp tile 32x16, split-tf32 3-pass ----
    float s_[2][2][4];
#pragma unroll
    for (int mi = 0; mi < 2; mi++)
#pragma unroll
      for (int ni = 0; ni < 2; ni++)
#pragma unroll
        for (int e = 0; e < 4; e++) s_[mi][ni][e] = 0.f;

#pragma unroll
    for (int kk = 0; kk < 128; kk += 8) {
      uint32_t ah[2][4], al[2][4], bh[2][2], bl[2][2];
#pragma unroll
      for (int mi = 0; mi < 2; mi++) {
        int r = wm + mi * 16 + g;
        split_tf32(Qs[r * ALDQ + kk + t],           ah[mi][0], al[mi][0]);
        split_tf32(Qs[(r + 8) * ALDQ + kk + t],     ah[mi][1], al[mi][1]);
        split_tf32(Qs[r * ALDQ + kk + t + 4],       ah[mi][2], al[mi][2]);
        split_tf32(Qs[(r + 8) * ALDQ + kk + t + 4], ah[mi][3], al[mi][3]);
      }
#pragma unroll
      for (int ni = 0; ni < 2; ni++) {
        int c = wnq + ni * 8 + g;
        split_tf32(Ks[c * ALDK + kk + t],     bh[ni][0], bl[ni][0]);
        split_tf32(Ks[c * ALDK + kk + t + 4], bh[ni][1], bl[ni][1]);
      }
#pragma unroll
      for (int mi = 0; mi < 2; mi++)
#pragma unroll
        for (int ni = 0; ni < 2; ni++) {
          mma_tf32(s_[mi][ni][0], s_[mi][ni][1], s_[mi][ni][2], s_[mi][ni][3],
                   ah[mi][0], ah[mi][1], ah[mi][2], ah[mi][3],
                   bh[ni][0], bh[ni][1]);
          mma_tf32(s_[mi][ni][0], s_[mi][ni][1], s_[mi][ni][2], s_[mi][ni][3],
                   ah[mi][0], ah[mi][1], ah[mi][2], ah[mi][3],
                   bl[ni][0], bl[ni][1]);
          mma_tf32(s_[mi][ni][0], s_[mi][ni][1], s_[mi][ni][2], s_[mi][ni][3],
                   al[mi][0], al[mi][1], al[mi][2], al[mi][3],
                   bh[ni][0], bh[ni][1]);
        }
    }
    __syncthreads();  // K reads done; buffer reusable for S

    // ---- scale + mask + stage S (128 x 64, stride SLD) ----
#pragma unroll
    for (int mi = 0; mi < 2; mi++) {
      int r = wm + mi * 16 + g;
      int qp0 = Ps[r], qp1 = Ps[r + 8];
#pragma unroll
      for (int ni = 0; ni < 2; ni++) {
        int c = wnq + ni * 8 + 2 * t;
        int kvp0 = kt * 64 + c, kvp1 = kvp0 + 1;
        float e0 = s_[mi][ni][0] * scale;
        float e1 = s_[mi][ni][1] * scale;
        float e2 = s_[mi][ni][2] * scale;
        float e3 = s_[mi][ni][3] * scale;
        if (kvp0 > qp0 || kvp0 >= kvl) e0 = -1e30f;
        if (kvp1 > qp0 || kvp1 >= kvl) e1 = -1e30f;
        if (kvp0 > qp1 || kvp0 >= kvl) e2 = -1e30f;
        if (kvp1 > qp1 || kvp1 >= kvl) e3 = -1e30f;
        *(float2*)(&Ss[r * SLD + c]) = make_float2(e0, e1);
        *(float2*)(&Ss[(r + 8) * SLD + c]) = make_float2(e2, e3);
      }
    }
    __syncthreads();

    // ---- online softmax: 4 threads/row, 16 cols each ----
    {
      int row = tid >> 2, seg = tid & 3;
      float* Sr = &Ss[row * SLD + seg * 16];
      float mx = -1e30f;
#pragma unroll
      for (int i4 = 0; i4 < 4; i4++) {
        float4 vv = *(float4*)(&Sr[i4 * 4]);
        mx = fmaxf(mx, fmaxf(fmaxf(vv.x, vv.y), fmaxf(vv.z, vv.w)));
      }
      mx = fmaxf(mx, __shfl_xor_sync(0xffffffffu, mx, 1));
      mx = fmaxf(mx, __shfl_xor_sync(0xffffffffu, mx, 2));
      float m_old = Ms[row];
      float m_new = fmaxf(m_old, mx);
      float sum = 0.f;
#pragma unroll
      for (int i4 = 0; i4 < 4; i4++) {
        float4 vv = *(float4*)(&Sr[i4 * 4]);
        vv.x = __expf(vv.x - m_new);
        vv.y = __expf(vv.y - m_new);
        vv.z = __expf(vv.z - m_new);
        vv.w = __expf(vv.w - m_new);
        *(float4*)(&Sr[i4 * 4]) = vv;
        sum += vv.x + vv.y + vv.z + vv.w;
      }
      sum += __shfl_xor_sync(0xffffffffu, sum, 1);
      sum += __shfl_xor_sync(0xffffffffu, sum, 2);
      if (seg == 0) {
        float alpha = __expf(m_old - m_new);
        Al[row] = alpha;
        Ls[row] = Ls[row] * alpha + sum;
        Ms[row] = m_new;
      }
    }
    __syncthreads();

    // ---- rescale O, then O += P(128x64) @ V(64x128), warp tile 32x32 ----
#pragma unroll
    for (int mi = 0; mi < 2; mi++) {
      int r = wm + mi * 16 + g;
      float a0 = Al[r], a1 = Al[r + 8];
#pragma unroll
      for (int ni = 0; ni < 4; ni++) {
        o[mi][ni][0] *= a0; o[mi][ni][1] *= a0;
        o[mi][ni][2] *= a1; o[mi][ni][3] *= a1;
      }
    }
#pragma unroll
    for (int kk = 0; kk < 64; kk += 8) {
      uint32_t ah[2][4], al[2][4], bh[4][2], bl[4][2];
#pragma unroll
      for (int mi = 0; mi < 2; mi++) {
        int r = wm + mi * 16 + g;
        split_tf32(Ss[r * SLD + kk + t],           ah[mi][0], al[mi][0]);
        split_tf32(Ss[(r + 8) * SLD + kk + t],     ah[mi][1], al[mi][1]);
        split_tf32(Ss[r * SLD + kk + t + 4],       ah[mi][2], al[mi][2]);
        split_tf32(Ss[(r + 8) * SLD + kk + t + 4], ah[mi][3], al[mi][3]);
      }
#pragma unroll
      for (int ni = 0; ni < 4; ni++) {
        int c = wnp + ni * 8 + g;
        split_tf32(Vs[(kk + t) * ALDV + c],     bh[ni][0], bl[ni][0]);
        split_tf32(Vs[(kk + t + 4) * ALDV + c], bh[ni][1], bl[ni][1]);
      }
#pragma unroll
      for (int mi = 0; mi < 2; mi++)
#pragma unroll
        for (int ni = 0; ni < 4; ni++) {
          mma_tf32(o[mi][ni][0], o[mi][ni][1], o[mi][ni][2], o[mi][ni][3],
                   ah[mi][0], ah[mi][1], ah[mi][2], ah[mi][3],
                   bh[ni][0], bh[ni][1]);
          mma_tf32(o[mi][ni][0], o[mi][ni][1], o[mi][ni][2], o[mi][ni][3],
                   ah[mi][0], ah[mi][1], ah[mi][2], ah[mi][3],
                   bl[ni][0], bl[ni][1]);
          mma_tf32(o[mi][ni][0], o[mi][ni][1], o[mi][ni][2], o[mi][ni][3],
                   al[mi][0], al[mi][1], al[mi][2], al[mi][3],
                   bh[ni][0], bh[ni][1]);
        }
    }
    __syncthreads();  // S/V reads done before tile kt+1's prefetch overwrites
  }

  // ---- normalize + tf32-round + write ----
#pragma unroll
  for (int mi = 0; mi < 2; mi++) {
    int r = wm + mi * 16 + g;
    float il0 = 1.f / Ls[r], il1 = 1.f / Ls[r + 8];
#pragma unroll
    for (int ni = 0; ni < 4; ni++) {
      int c = wnp + ni * 8 + 2 * t;
      float* d0 = g_attn + (size_t)(t_base + r) * HIDDEN + h * HD + c;
      float* d1 = g_attn + (size_t)(t_base + r + 8) * HIDDEN + h * HD + c;
      *(float2*)d0 = make_float2(f2tf_f(o[mi][ni][0] * il0), f2tf_f(o[mi][ni][1] * il0));
      *(float2*)d1 = make_float2(f2tf_f(o[mi][ni][2] * il1), f2tf_f(o[mi][ni][3] * il1));
    }
  }
}

// ============================================================================
extern "C" void kernel_launch(void* const* d_in, const int* in_sizes, int n_in,
                              void* d_out, int out_size) {
  const float* hidden = (const float*)d_in[0];
  const float* Wq = (const float*)d_in[1];
  const float* Wk = (const float*)d_in[2];
  const float* Wv = (const float*)d_in[3];
  const float* Wo = (const float*)d_in[4];
  const float* kc = (const float*)d_in[5];
  const float* vc = (const float*)d_in[6];
  const int* btab = (const int*)d_in[7];
  const int* pos = (const int*)d_in[8];
  const int* kvlen = (const int*)d_in[9];
  float* out = (float*)d_out;

  float *q, *k, *v, *attn, *hid_t, *wq_t, *wk_t, *wv_t, *wo_t;
  cudaGetSymbolAddress((void**)&q, g_q);
  cudaGetSymbolAddress((void**)&k, g_k);
  cudaGetSymbolAddress((void**)&v, g_v);
  cudaGetSymbolAddress((void**)&attn, g_attn);
  cudaGetSymbolAddress((void**)&hid_t, g_hid_t);
  cudaGetSymbolAddress((void**)&wq_t, g_wq_t);
  cudaGetSymbolAddress((void**)&wk_t, g_wk_t);
  cudaGetSymbolAddress((void**)&wv_t, g_wv_t);
  cudaGetSymbolAddress((void**)&wo_t, g_wo_t);

  cudaFuncSetAttribute(gemm_tf32, cudaFuncAttributeMaxDynamicSharedMemorySize,
                       GEMM_SMEM_BYTES);
  cudaFuncSetAttribute(attn_kernel, cudaFuncAttributeMaxDynamicSharedMemorySize,
                       ATTN_SMEM_FLOATS * 4);

  // one batched cvt launch (index 0) -> gemms occupy launch indices 1-3
  int cvt_grid = (int)((MAT_ELEMS / 4 + 255) / 256);
  {
    dim3 gc(cvt_grid, 4);
    cvt4_kernel<<<gc, 256>>>((const float4*)hidden, (const float4*)Wq,
                             (const float4*)Wk, (const float4*)Wv);
  }

  dim3 gg(32, 32);  // N/128, M/128
  gemm_tf32<<<gg, 256, GEMM_SMEM_BYTES>>>(hid_t, wq_t, q);
  gemm_tf32<<<gg, 256, GEMM_SMEM_BYTES>>>(hid_t, wk_t, k);
  gemm_tf32<<<gg, 256, GEMM_SMEM_BYTES>>>(hid_t, wv_t, v);

  rope_kernel<<<(T_TOK * NH * 64 + 255) / 256, 256>>>(q, k, pos);

  dim3 ga(4, NH, B_SEQ);  // (q-tile of 128, head, seq)
  attn_kernel<<<ga, 512, ATTN_SMEM_FLOATS * 4>>>(kc, vc, btab, pos, kvlen);

  cvt_tf32_kernel<<<cvt_grid, 256>>>((const float4*)Wo, (float4*)wo_t);
  gemm_tf32<<<gg, 256, GEMM_SMEM_BYTES>>>(attn, wo_t, out);
}